// round 11
// baseline (speedup 1.0000x reference)
#include <cuda_runtime.h>

// x: (4, 32, 512, 512) fp32 ; bias: (1, 32, 1, 1) fp32
// out: [G1 | G2 | G3], each (4, 32, 512, 512) fp32
//
// G1[h,w] = (h>=1 && w>=1) ? exp(-(x[h-1,w-1]-x[h,w])^2) + bias : bias
// G2[h,w] = (w>=1)          ? exp(-(x[h,  w-1]-x[h,w])^2) + bias : bias
// G3[h,w] = (h<H-1 && w>=1) ? exp(-(x[h+1,w-1]-x[h,w])^2) + bias : bias
//
// One float4 per thread, branchless. x (134MB) doesn't fit L2 (126MB) and a
// cyclic re-scan under uniform priority churns; a range policy pins a 96MB
// prefix of x (evict_last) and streams the tail (evict_first), cutting DRAM
// read misses across graph replays. Outputs write-through (never re-read).

#define H   512
#define WV  128           // float4 per row
#define N4  8388608u      // float4 per gate tensor (4*32*512*512/4)

#define PRIM_BYTES  0x06000000u   // 96 MB evict_last prefix
#define TOTAL_BYTES 0x08000000u   // 128 MB policy window (tail = evict_first)

__device__ __forceinline__ unsigned long long mk_range_policy(const float* base) {
    unsigned long long pol;
    asm("createpolicy.range.L2::evict_last.L2::evict_first.b64 %0, [%1], %2, %3;"
        : "=l"(pol) : "l"(base), "r"(PRIM_BYTES), "r"(TOTAL_BYTES));
    return pol;
}
__device__ __forceinline__ float4 ldg_ch_v4(const float4* p, unsigned long long pol) {
    float4 r;
    asm volatile("ld.global.nc.L2::cache_hint.v4.f32 {%0,%1,%2,%3}, [%4], %5;"
                 : "=f"(r.x), "=f"(r.y), "=f"(r.z), "=f"(r.w)
                 : "l"(p), "l"(pol));
    return r;
}
__device__ __forceinline__ float ldg_ch_f(const float* p, unsigned long long pol) {
    float r;
    asm volatile("ld.global.nc.L2::cache_hint.f32 %0, [%1], %2;"
                 : "=f"(r) : "l"(p), "l"(pol));
    return r;
}

__global__ __launch_bounds__(256) void embeded_gate_kernel(
    const float* __restrict__ x,
    const float* __restrict__ bias,
    float* __restrict__ out)
{
    const unsigned idx = blockIdx.x * 256u + threadIdx.x;   // == float4 linear index
    const unsigned v = idx & (WV - 1);
    const unsigned h = (idx >> 7) & (H - 1);
    const unsigned c = (idx >> 16) & 31u;

    const float bi = __ldg(&bias[c]);
    const unsigned long long pol = mk_range_policy(x);

    const bool hup = (h > 0);
    const bool hdn = (h < H - 1);
    const bool vs  = (v > 0);

    // clamped neighbor-row float4 indices (always in-bounds)
    const unsigned iu = hup ? idx - WV : idx;
    const unsigned id = hdn ? idx + WV : idx;
    const unsigned dv = vs ? 1u : 0u;   // scalar left-neighbor offset

    const float4* __restrict__ x4 = reinterpret_cast<const float4*>(x);

    // ---- 6 unconditional, independent loads (front-batched) ----
    const float4 cur4 = ldg_ch_v4(&x4[idx], pol);
    const float4 u4   = ldg_ch_v4(&x4[iu],  pol);
    const float4 d4   = ldg_ch_v4(&x4[id],  pol);
    const float  lc   = ldg_ch_f(&x[(idx << 2) - dv], pol);
    const float  lu   = ldg_ch_f(&x[(iu  << 2) - dv], pol);
    const float  ld   = ldg_ch_f(&x[(id  << 2) - dv], pol);

    const float cur[4] = {cur4.x, cur4.y, cur4.z, cur4.w};
    const float lf[4]  = {lc, cur4.x, cur4.y, cur4.z};
    const float up[4]  = {lu, u4.x,   u4.y,   u4.z};
    const float dn[4]  = {ld, d4.x,   d4.y,   d4.z};

    float g1[4], g2[4], g3[4];
#pragma unroll
    for (int k = 0; k < 4; ++k) {
        const bool wok = vs || (k > 0);     // global w index > 0
        float e1 = up[k] - cur[k];
        float e2 = lf[k] - cur[k];
        float e3 = dn[k] - cur[k];
        float v1 = __expf(-e1 * e1) + bi;
        float v2 = __expf(-e2 * e2) + bi;
        float v3 = __expf(-e3 * e3) + bi;
        g1[k] = (hup && wok) ? v1 : bi;
        g2[k] = (wok)        ? v2 : bi;
        g3[k] = (hdn && wok) ? v3 : bi;
    }

    float4* __restrict__ o4 = reinterpret_cast<float4*>(out);
    __stwt(&o4[idx],           make_float4(g1[0], g1[1], g1[2], g1[3]));
    __stwt(&o4[idx + N4],      make_float4(g2[0], g2[1], g2[2], g2[3]));
    __stwt(&o4[idx + 2u * N4], make_float4(g3[0], g3[1], g3[2], g3[3]));
}

extern "C" void kernel_launch(void* const* d_in, const int* in_sizes, int n_in,
                              void* d_out, int out_size) {
    const float* x    = (const float*)d_in[0];
    const float* bias = (const float*)d_in[1];
    float* out = (float*)d_out;

    const long long total_vec = (long long)in_sizes[0] / 4;   // 8,388,608 threads
    const int threads = 256;
    const int blocks = (int)((total_vec + threads - 1) / threads);

    embeded_gate_kernel<<<blocks, threads>>>(x, bias, out);
}

// round 12
// speedup vs baseline: 1.0070x; 1.0070x over previous
#include <cuda_runtime.h>

// x: (4, 32, 512, 512) fp32 ; bias: (1, 32, 1, 1) fp32
// out: [G1 | G2 | G3], each (4, 32, 512, 512) fp32
//
// G1[h,w] = (h>=1 && w>=1) ? exp(-(x[h-1,w-1]-x[h,w])^2) + bias : bias
// G2[h,w] = (w>=1)          ? exp(-(x[h,  w-1]-x[h,w])^2) + bias : bias
// G3[h,w] = (h<H-1 && w>=1) ? exp(-(x[h+1,w-1]-x[h,w])^2) + bias : bias
//
// CONVERGED KERNEL (R5 config). This op is DRAM-write-bound: 403 MB of
// output vs ~75 MB of read misses; seven variants (block 128/256/512,
// 128/256-bit transactions, shuffle left-neighbors, evict_last / range
// cache policies, stcs/stwt/default stores, h-pair blocking) all pin at
// 6.0-6.07 TB/s and ~76% DRAM busy -> controller equilibrium for this
// read:write mix. One float4 per thread, fully branchless (clamped row
// indices + selects), write-through stores.

#define H   512
#define WV  128           // float4 per row
#define N4  8388608u      // float4 per gate tensor (4*32*512*512/4)

__global__ __launch_bounds__(256) void embeded_gate_kernel(
    const float* __restrict__ x,
    const float* __restrict__ bias,
    float* __restrict__ out)
{
    const unsigned idx = blockIdx.x * 256u + threadIdx.x;   // == float4 linear index
    const unsigned v = idx & (WV - 1);
    const unsigned h = (idx >> 7) & (H - 1);
    const unsigned c = (idx >> 16) & 31u;

    const float bi = __ldg(&bias[c]);

    const bool hup = (h > 0);
    const bool hdn = (h < H - 1);
    const bool vs  = (v > 0);

    // clamped neighbor-row float4 indices (always in-bounds)
    const unsigned iu = hup ? idx - WV : idx;
    const unsigned id = hdn ? idx + WV : idx;
    const unsigned dv = vs ? 1u : 0u;   // scalar left-neighbor offset

    const float4* __restrict__ x4 = reinterpret_cast<const float4*>(x);

    // ---- 6 unconditional, independent loads (front-batched) ----
    const float4 cur4 = x4[idx];
    const float4 u4   = x4[iu];
    const float4 d4   = x4[id];
    const float  lc   = __ldg(&x[(idx << 2) - dv]);
    const float  lu   = __ldg(&x[(iu  << 2) - dv]);
    const float  ld   = __ldg(&x[(id  << 2) - dv]);

    const float cur[4] = {cur4.x, cur4.y, cur4.z, cur4.w};
    const float lf[4]  = {lc, cur4.x, cur4.y, cur4.z};
    const float up[4]  = {lu, u4.x,   u4.y,   u4.z};
    const float dn[4]  = {ld, d4.x,   d4.y,   d4.z};

    float g1[4], g2[4], g3[4];
#pragma unroll
    for (int k = 0; k < 4; ++k) {
        const bool wok = vs || (k > 0);     // global w index > 0
        float e1 = up[k] - cur[k];
        float e2 = lf[k] - cur[k];
        float e3 = dn[k] - cur[k];
        float v1 = __expf(-e1 * e1) + bi;
        float v2 = __expf(-e2 * e2) + bi;
        float v3 = __expf(-e3 * e3) + bi;
        g1[k] = (hup && wok) ? v1 : bi;
        g2[k] = (wok)        ? v2 : bi;
        g3[k] = (hdn && wok) ? v3 : bi;
    }

    float4* __restrict__ o4 = reinterpret_cast<float4*>(out);
    __stwt(&o4[idx],           make_float4(g1[0], g1[1], g1[2], g1[3]));
    __stwt(&o4[idx + N4],      make_float4(g2[0], g2[1], g2[2], g2[3]));
    __stwt(&o4[idx + 2u * N4], make_float4(g3[0], g3[1], g3[2], g3[3]));
}

extern "C" void kernel_launch(void* const* d_in, const int* in_sizes, int n_in,
                              void* d_out, int out_size) {
    const float* x    = (const float*)d_in[0];
    const float* bias = (const float*)d_in[1];
    float* out = (float*)d_out;

    const long long total_vec = (long long)in_sizes[0] / 4;   // 8,388,608 threads
    const int threads = 256;
    const int blocks = (int)((total_vec + threads - 1) / threads);

    embeded_gate_kernel<<<blocks, threads>>>(x, bias, out);
}

// round 13
// speedup vs baseline: 1.0113x; 1.0043x over previous
#include <cuda_runtime.h>

// x: (4, 32, 512, 512) fp32 ; bias: (1, 32, 1, 1) fp32
// out: [G1 | G2 | G3], each (4, 32, 512, 512) fp32
//
// G1[h,w] = (h>=1 && w>=1) ? exp(-(x[h-1,w-1]-x[h,w])^2) + bias : bias
// G2[h,w] = (w>=1)          ? exp(-(x[h,  w-1]-x[h,w])^2) + bias : bias
// G3[h,w] = (h<H-1 && w>=1) ? exp(-(x[h+1,w-1]-x[h,w])^2) + bias : bias
//
// Converged config: one float4 per thread, branchless (clamped row indices
// + selects), 256-thread blocks. Final isolated delta: __stcs stores
// (evict-first but L2-write-buffered, preserving L2 burst forming toward
// the DRAM controller) vs R5's write-through.
//
// Measured landscape: 403 MB writes dominate; seven structural variants all
// pin at 6.0-6.07 TB/s, ~76% DRAM busy -> HBM RW-turnaround equilibrium.

#define H   512
#define WV  128           // float4 per row
#define N4  8388608u      // float4 per gate tensor (4*32*512*512/4)

__global__ __launch_bounds__(256) void embeded_gate_kernel(
    const float* __restrict__ x,
    const float* __restrict__ bias,
    float* __restrict__ out)
{
    const unsigned idx = blockIdx.x * 256u + threadIdx.x;   // == float4 linear index
    const unsigned v = idx & (WV - 1);
    const unsigned h = (idx >> 7) & (H - 1);
    const unsigned c = (idx >> 16) & 31u;

    const float bi = __ldg(&bias[c]);

    const bool hup = (h > 0);
    const bool hdn = (h < H - 1);
    const bool vs  = (v > 0);

    // clamped neighbor-row float4 indices (always in-bounds)
    const unsigned iu = hup ? idx - WV : idx;
    const unsigned id = hdn ? idx + WV : idx;
    const unsigned dv = vs ? 1u : 0u;   // scalar left-neighbor offset

    const float4* __restrict__ x4 = reinterpret_cast<const float4*>(x);

    // ---- 6 unconditional, independent loads (front-batched) ----
    const float4 cur4 = x4[idx];
    const float4 u4   = x4[iu];
    const float4 d4   = x4[id];
    const float  lc   = __ldg(&x[(idx << 2) - dv]);
    const float  lu   = __ldg(&x[(iu  << 2) - dv]);
    const float  ld   = __ldg(&x[(id  << 2) - dv]);

    const float cur[4] = {cur4.x, cur4.y, cur4.z, cur4.w};
    const float lf[4]  = {lc, cur4.x, cur4.y, cur4.z};
    const float up[4]  = {lu, u4.x,   u4.y,   u4.z};
    const float dn[4]  = {ld, d4.x,   d4.y,   d4.z};

    float g1[4], g2[4], g3[4];
#pragma unroll
    for (int k = 0; k < 4; ++k) {
        const bool wok = vs || (k > 0);     // global w index > 0
        float e1 = up[k] - cur[k];
        float e2 = lf[k] - cur[k];
        float e3 = dn[k] - cur[k];
        float v1 = __expf(-e1 * e1) + bi;
        float v2 = __expf(-e2 * e2) + bi;
        float v3 = __expf(-e3 * e3) + bi;
        g1[k] = (hup && wok) ? v1 : bi;
        g2[k] = (wok)        ? v2 : bi;
        g3[k] = (hdn && wok) ? v3 : bi;
    }

    float4* __restrict__ o4 = reinterpret_cast<float4*>(out);
    __stcs(&o4[idx],           make_float4(g1[0], g1[1], g1[2], g1[3]));
    __stcs(&o4[idx + N4],      make_float4(g2[0], g2[1], g2[2], g2[3]));
    __stcs(&o4[idx + 2u * N4], make_float4(g3[0], g3[1], g3[2], g3[3]));
}

extern "C" void kernel_launch(void* const* d_in, const int* in_sizes, int n_in,
                              void* d_out, int out_size) {
    const float* x    = (const float*)d_in[0];
    const float* bias = (const float*)d_in[1];
    float* out = (float*)d_out;

    const long long total_vec = (long long)in_sizes[0] / 4;   // 8,388,608 threads
    const int threads = 256;
    const int blocks = (int)((total_vec + threads - 1) / threads);

    embeded_gate_kernel<<<blocks, threads>>>(x, bias, out);
}